// round 12
// baseline (speedup 1.0000x reference)
#include <cuda_runtime.h>
#include <cuda_fp16.h>
#include <cstdint>
#include <math.h>

// Histogram2D via first-moment particle deposit + exact separable erf-CDF
// convolution with derivative correction, q=4 fine cells per bin.
// Three kernels:
//   1) k_deposit: ONE red.global.add.noftz.v2.f16x2 per point into an 8-byte
//      fine cell (count, dy, dx in f16; count is exact — sums of 1.0 < 2048),
//      4 points per thread for MLP. Last block builds W/W'/Cw/Cwp, resets g_sum.
//   2) k_pass1: reduce fx -> (Ba,Bb)[ix][fy]; each CTA adds its exact share of
//      the normalization sum to g_sum (16 atomics total).
//   3) k_pass2: reduce fy (256 thr: taps split in half per iy), scale inline,
//      re-zero the fine grid for the next graph replay.
// Error model (validated R7-R10): ~1.46e-4 at q=4 with f16 moments.

#define NB    128
#define Q     4
#define PADB  8                     // padding in bins
#define PAD   (PADB*Q)              // 32 fine cells
#define NF    (NB*Q + 2*PAD)        // 576 fine cells per axis
#define TAP0  12                    // first tap (zc = -4.875 bins)
#define NTAP  44                    // support ~ +/-5 bins (tail < 3e-7)
#define ISEG  8                     // ix outputs per pass1 CTA
#define ERANGE (Q*ISEG + NTAP - Q)  // 72 fine rows read per pass1 CTA (8*9)

__device__ float4 g_fg4[(NF * NF) / 2]; // fine grid, 2 cells per float4, 2.65 MB
__device__ float2 g_Bt2[NB * NF];       // pass1 output (Ba,Bb)[ix][fy], 590 KB
__device__ float  g_W[64];              // kernel tap table (bin units)
__device__ float  g_Wp[64];             // d/dz of tap table
__device__ float  g_Cw[NF];             // Cw[fy]  = sum_iy W (fy - Q*iy - TAP0)
__device__ float  g_Cwp[NF];            // Cwp[fy] = sum_iy W'(fy - Q*iy - TAP0)
__device__ float  g_sum;

// ---------------------------------------------------------------------------
// Kernel 1: deposit (blocks [0, G-1)) + table block (last block).
__global__ __launch_bounds__(256)
void k_deposit(const float* __restrict__ x,
               const float* __restrict__ ex,
               const float* __restrict__ ey,
               int n)
{
    if (blockIdx.x == gridDim.x - 1) {
        const int tid = threadIdx.x;
        if (tid < 64) {
            float zc = ((float)tid + 0.5f) * (1.0f / (float)Q) - (float)PADB;
            const float is2 = 0.70710678118654752f;     // 1/sqrt(2), sigma=1 bin
            g_W[tid] = 0.5f * (erff((1.0f - zc) * is2) - erff((-zc) * is2));
            const float inv_s2pi = 0.3989422804014327f; // 1/sqrt(2*pi)
            g_Wp[tid] = inv_s2pi * (expf(-0.5f * zc * zc)
                                  - expf(-0.5f * (1.0f - zc) * (1.0f - zc)));
        }
        if (tid == 64) g_sum = 0.0f;
        __syncthreads();
        for (int fy = tid; fy < NF; fy += 256) {
            float cw = 0.f, cwp = 0.f;
            #pragma unroll 4
            for (int iy = 0; iy < NB; iy++) {
                int t = fy - Q * iy - TAP0;
                if (t >= 0 && t < NTAP) {
                    cw  += g_W[TAP0 + t];
                    cwp += g_Wp[TAP0 + t];
                }
            }
            g_Cw[fy]  = cw;
            g_Cwp[fy] = cwp;
        }
        return;
    }

    const float lox = ex[0], dx = ex[1] - ex[0];
    const float loy = ey[0], dy = ey[1] - ey[0];
    const float sx = (float)Q / dx;
    const float sy = (float)Q / dy;

    // 4 points per thread; all loads issued up front (MLP=4).
    const int base = blockIdx.x * 1024 + threadIdx.x;
    float2 u[4];
    #pragma unroll
    for (int k = 0; k < 4; k++) {
        int p = base + k * 256;
        u[k] = (p < n) ? *reinterpret_cast<const float2*>(x + (size_t)p * 6)
                       : make_float2(1e30f, 1e30f);   // lands out of range
    }

    #pragma unroll
    for (int k = 0; k < 4; k++) {
        float pfx = (u[k].x - lox) * sx + (float)PAD;
        float pfy = (u[k].y - loy) * sy + (float)PAD;
        float cfx = floorf(pfx), cfy = floorf(pfy);
        int cx = (int)cfx, cy = (int)cfy;
        if ((unsigned)cx >= NF || (unsigned)cy >= NF) continue;

        float dxb = (pfx - cfx - 0.5f) * (1.0f / (float)Q);    // bin units
        float dyb = (pfy - cfy - 0.5f) * (1.0f / (float)Q);

        // cell = [count | dyb | dxb | pad] as 2 x f16x2, ONE vector RED.
        __half2 h0 = __floats2half2_rn(1.0f, dyb);   // low = count, high = M01
        __half2 h1 = __floats2half2_rn(dxb, 0.0f);   // low = M10
        uint32_t r0 = *reinterpret_cast<uint32_t*>(&h0);
        uint32_t r1 = *reinterpret_cast<uint32_t*>(&h1);
        char* cell = reinterpret_cast<char*>(g_fg4) + ((size_t)cx * NF + cy) * 8;
        asm volatile("red.global.add.noftz.v2.f16x2 [%0], {%1, %2};"
                     :: "l"(cell), "r"(r0), "r"(r1) : "memory");
    }
}

// ---------------------------------------------------------------------------
// Kernel 2: reduce fx; halo-redundant reads, no atomics on Bt.
// Also accumulates this CTA's exact share of the final sum into g_sum.
__global__ __launch_bounds__(64)
void k_pass1()
{
    __shared__ float sW[NTAP], sWp[NTAP];
    __shared__ float sred[64];
    if (threadIdx.x < NTAP) {
        sW[threadIdx.x]  = g_W[TAP0 + threadIdx.x];
        sWp[threadIdx.x] = g_Wp[TAP0 + threadIdx.x];
    }
    __syncthreads();

    const int fy = blockIdx.y * 64 + threadIdx.x;   // < NF (9*64 = 576)
    const int I0 = blockIdx.x * ISEG;
    const uint2* col = reinterpret_cast<const uint2*>(g_fg4) + fy;

    float2 acc[ISEG];
    #pragma unroll
    for (int s = 0; s < ISEG; s++) acc[s] = make_float2(0.f, 0.f);

    #pragma unroll 8
    for (int e = 0; e < ERANGE; e++) {
        const int fx = I0 * Q + TAP0 + e;           // max 563 < NF
        uint2 c = col[(size_t)fx * NF];
        __half2 h0 = *reinterpret_cast<__half2*>(&c.x);
        __half2 h1 = *reinterpret_cast<__half2*>(&c.y);
        float2 f0 = __half22float2(h0);             // (M00, M01)
        float2 f1 = __half22float2(h1);             // (M10, -)
        #pragma unroll
        for (int s = 0; s < ISEG; s++) {
            int t = e - Q * s;                      // tap offset from TAP0
            if (t >= 0 && t < NTAP) {
                acc[s].x = fmaf(sW[t], f0.x, fmaf(sWp[t], f1.x, acc[s].x));
                acc[s].y = fmaf(sW[t], f0.y, acc[s].y);
            }
        }
    }

    float pa = 0.f, pb = 0.f;
    #pragma unroll
    for (int s = 0; s < ISEG; s++) {
        g_Bt2[(size_t)(I0 + s) * NF + fy] = acc[s];
        pa += acc[s].x;
        pb += acc[s].y;
    }

    sred[threadIdx.x] = g_Cw[fy] * pa + g_Cwp[fy] * pb;
    __syncthreads();
    #pragma unroll
    for (int off = 32; off > 0; off >>= 1) {
        if (threadIdx.x < off) sred[threadIdx.x] += sred[threadIdx.x + off];
        __syncthreads();
    }
    if (threadIdx.x == 0) atomicAdd(&g_sum, sred[0]);
}

// ---------------------------------------------------------------------------
// Kernel 3: reduce fy with 256 threads (taps split in half per iy), scale
// inline (g_sum final at launch), zero g_fg for the next replay.
#define SPAD(i) ((i) + ((i) >> 2))
__global__ __launch_bounds__(256)
void k_pass2(float* __restrict__ out,
             const float* __restrict__ ex,
             const float* __restrict__ ey)
{
    __shared__ float sW[NTAP], sWp[NTAP];
    __shared__ float sBa[NF + NF / 4], sBb[NF + NF / 4];
    __shared__ float sPart[256];
    __shared__ float s_scale;

    const int tid = threadIdx.x;
    const int ix  = blockIdx.x;
    const int iy  = tid & 127;
    const int hf  = tid >> 7;

    if (tid < NTAP) { sW[tid] = g_W[TAP0 + tid]; sWp[tid] = g_Wp[TAP0 + tid]; }
    if (tid == 255) {
        float dxw = ex[1] - ex[0];
        float dyw = ey[1] - ey[0];
        s_scale = 1.0f / (g_sum * dxw * dyw);
    }
    const float2* brow = g_Bt2 + (size_t)ix * NF;
    #pragma unroll
    for (int i = tid; i < NF; i += 256) {
        float2 v = brow[i];
        sBa[SPAD(i)] = v.x;
        sBb[SPAD(i)] = v.y;
    }
    __syncthreads();

    const int t0   = hf * (NTAP / 2);
    const int base = Q * iy + TAP0;                 // max fy index 563 < NF
    float a0 = 0.f, a1 = 0.f;
    #pragma unroll
    for (int t = t0; t < t0 + NTAP / 2; t += 2) {
        a0 = fmaf(sW[t+0], sBa[SPAD(base+t+0)], fmaf(sWp[t+0], sBb[SPAD(base+t+0)], a0));
        a1 = fmaf(sW[t+1], sBa[SPAD(base+t+1)], fmaf(sWp[t+1], sBb[SPAD(base+t+1)], a1));
    }
    sPart[tid] = a0 + a1;
    __syncthreads();
    if (tid < 128)
        out[(size_t)ix * NB + tid] = (sPart[tid] + sPart[tid + 128]) * s_scale;

    // Re-zero the fine grid for the next replay (coalesced float4 stores).
    const float4 z = make_float4(0.f, 0.f, 0.f, 0.f);
    for (int i = ix * 256 + tid; i < (NF * NF) / 2; i += NB * 256)
        g_fg4[i] = z;
}

// ---------------------------------------------------------------------------
extern "C" void kernel_launch(void* const* d_in, const int* in_sizes, int n_in,
                              void* d_out, int out_size)
{
    const float* x  = (const float*)d_in[0];
    const float* ex = (const float*)d_in[1];
    const float* ey = (const float*)d_in[2];
    float* out = (float*)d_out;

    int n = in_sizes[0] / 6;

    k_deposit<<<(n + 1023) / 1024 + 1, 256>>>(x, ex, ey, n);
    k_pass1<<<dim3(NB / ISEG, NF / 64), 64>>>();
    k_pass2<<<NB, 256>>>(out, ex, ey);
}

// round 13
// speedup vs baseline: 1.0617x; 1.0617x over previous
#include <cuda_runtime.h>
#include <cuda_fp16.h>
#include <cstdint>
#include <math.h>

// Histogram2D via first-moment particle deposit + exact separable erf-CDF
// convolution with derivative correction, q=4 fine cells per bin.
// Four kernels:
//   0) k_zero: zero fine grid (high parallelism), build W/W'/Cw/Cwp, reset g_sum
//   1) k_deposit: ONE red.global.add.noftz.v2.f16x2 per point into an 8-byte
//      fine cell (count/dy/dx in f16; count exact), 2 pts/thread, ~977 CTAs.
//   2) k_pass1: reduce fx -> (Ba,Bb)[ix][fy], ISEG=4 (288 CTAs); each CTA adds
//      its exact share of the normalization sum to g_sum.
//   3) k_pass2: reduce fy (256 thr, taps split in half per iy), scale inline.
// Error model (validated R7-R12): ~1.46e-4 at q=4 with f16 moments.

#define NB    128
#define Q     4
#define PADB  8                     // padding in bins
#define PAD   (PADB*Q)              // 32 fine cells
#define NF    (NB*Q + 2*PAD)        // 576 fine cells per axis
#define TAP0  12                    // first tap (zc = -4.875 bins)
#define NTAP  44                    // support ~ +/-5 bins (tail < 3e-7)
#define ISEG  4                     // ix outputs per pass1 CTA
#define ERANGE (Q*ISEG + NTAP - Q)  // 56 fine rows read per pass1 CTA

__device__ float4 g_fg4[(NF * NF) / 2]; // fine grid, 2 cells per float4, 2.65 MB
__device__ float2 g_Bt2[NB * NF];       // pass1 output (Ba,Bb)[ix][fy], 590 KB
__device__ float  g_W[64];              // kernel tap table (bin units)
__device__ float  g_Wp[64];             // d/dz of tap table
__device__ float  g_Cw[NF];             // Cw[fy]  = sum_iy W (fy - Q*iy - TAP0)
__device__ float  g_Cwp[NF];            // Cwp[fy] = sum_iy W'(fy - Q*iy - TAP0)
__device__ float  g_sum;

// ---------------------------------------------------------------------------
// Kernel 0: zero the fine grid; block 0 also builds tables and resets g_sum.
__global__ __launch_bounds__(256)
void k_zero()
{
    const float4 z = make_float4(0.f, 0.f, 0.f, 0.f);
    const int total = (NF * NF) / 2;
    for (int i = blockIdx.x * 256 + threadIdx.x; i < total; i += gridDim.x * 256)
        g_fg4[i] = z;

    if (blockIdx.x == 0) {
        const int tid = threadIdx.x;
        if (tid < 64) {
            float zc = ((float)tid + 0.5f) * (1.0f / (float)Q) - (float)PADB;
            const float is2 = 0.70710678118654752f;     // 1/sqrt(2), sigma=1 bin
            g_W[tid] = 0.5f * (erff((1.0f - zc) * is2) - erff((-zc) * is2));
            const float inv_s2pi = 0.3989422804014327f; // 1/sqrt(2*pi)
            g_Wp[tid] = inv_s2pi * (expf(-0.5f * zc * zc)
                                  - expf(-0.5f * (1.0f - zc) * (1.0f - zc)));
        }
        if (tid == 64) g_sum = 0.0f;
        __syncthreads();
        for (int fy = tid; fy < NF; fy += 256) {
            float cw = 0.f, cwp = 0.f;
            #pragma unroll 4
            for (int iy = 0; iy < NB; iy++) {
                int t = fy - Q * iy - TAP0;
                if (t >= 0 && t < NTAP) {
                    cw  += g_W[TAP0 + t];
                    cwp += g_Wp[TAP0 + t];
                }
            }
            g_Cw[fy]  = cw;
            g_Cwp[fy] = cwp;
        }
    }
}

// ---------------------------------------------------------------------------
// Kernel 1: deposit, 2 points per thread, one vector RED per point.
__global__ __launch_bounds__(256)
void k_deposit(const float* __restrict__ x,
               const float* __restrict__ ex,
               const float* __restrict__ ey,
               int n)
{
    const float lox = ex[0], dx = ex[1] - ex[0];
    const float loy = ey[0], dy = ey[1] - ey[0];
    const float sx = (float)Q / dx;
    const float sy = (float)Q / dy;

    const int base = blockIdx.x * 512 + threadIdx.x;
    float2 u[2];
    #pragma unroll
    for (int k = 0; k < 2; k++) {
        int p = base + k * 256;
        u[k] = (p < n) ? *reinterpret_cast<const float2*>(x + (size_t)p * 6)
                       : make_float2(1e30f, 1e30f);   // lands out of range
    }

    #pragma unroll
    for (int k = 0; k < 2; k++) {
        float pfx = (u[k].x - lox) * sx + (float)PAD;
        float pfy = (u[k].y - loy) * sy + (float)PAD;
        float cfx = floorf(pfx), cfy = floorf(pfy);
        int cx = (int)cfx, cy = (int)cfy;
        if ((unsigned)cx >= NF || (unsigned)cy >= NF) continue;

        float dxb = (pfx - cfx - 0.5f) * (1.0f / (float)Q);    // bin units
        float dyb = (pfy - cfy - 0.5f) * (1.0f / (float)Q);

        // cell = [count | dyb | dxb | pad] as 2 x f16x2, ONE vector RED.
        __half2 h0 = __floats2half2_rn(1.0f, dyb);   // low = count, high = M01
        __half2 h1 = __floats2half2_rn(dxb, 0.0f);   // low = M10
        uint32_t r0 = *reinterpret_cast<uint32_t*>(&h0);
        uint32_t r1 = *reinterpret_cast<uint32_t*>(&h1);
        char* cell = reinterpret_cast<char*>(g_fg4) + ((size_t)cx * NF + cy) * 8;
        asm volatile("red.global.add.noftz.v2.f16x2 [%0], {%1, %2};"
                     :: "l"(cell), "r"(r0), "r"(r1) : "memory");
    }
}

// ---------------------------------------------------------------------------
// Kernel 2: reduce fx; halo-redundant reads, no atomics on Bt.
// ISEG=4 -> 32 x-segments x 9 fy-tiles = 288 CTAs of 64 threads.
// Also accumulates this CTA's exact share of the final sum into g_sum.
__global__ __launch_bounds__(64)
void k_pass1()
{
    __shared__ float sW[NTAP], sWp[NTAP];
    __shared__ float sred[64];
    if (threadIdx.x < NTAP) {
        sW[threadIdx.x]  = g_W[TAP0 + threadIdx.x];
        sWp[threadIdx.x] = g_Wp[TAP0 + threadIdx.x];
    }
    __syncthreads();

    const int fy = blockIdx.y * 64 + threadIdx.x;   // < NF (9*64 = 576)
    const int I0 = blockIdx.x * ISEG;
    const uint2* col = reinterpret_cast<const uint2*>(g_fg4) + fy;

    float2 acc[ISEG];
    #pragma unroll
    for (int s = 0; s < ISEG; s++) acc[s] = make_float2(0.f, 0.f);

    #pragma unroll 4
    for (int e = 0; e < ERANGE; e++) {
        const int fx = I0 * Q + TAP0 + e;           // max 124*4+12+55 = 563 < NF
        uint2 c = col[(size_t)fx * NF];
        __half2 h0 = *reinterpret_cast<__half2*>(&c.x);
        __half2 h1 = *reinterpret_cast<__half2*>(&c.y);
        float2 f0 = __half22float2(h0);             // (M00, M01)
        float2 f1 = __half22float2(h1);             // (M10, -)
        #pragma unroll
        for (int s = 0; s < ISEG; s++) {
            int t = e - Q * s;                      // tap offset from TAP0
            if (t >= 0 && t < NTAP) {
                acc[s].x = fmaf(sW[t], f0.x, fmaf(sWp[t], f1.x, acc[s].x));
                acc[s].y = fmaf(sW[t], f0.y, acc[s].y);
            }
        }
    }

    float pa = 0.f, pb = 0.f;
    #pragma unroll
    for (int s = 0; s < ISEG; s++) {
        g_Bt2[(size_t)(I0 + s) * NF + fy] = acc[s];
        pa += acc[s].x;
        pb += acc[s].y;
    }

    sred[threadIdx.x] = g_Cw[fy] * pa + g_Cwp[fy] * pb;
    __syncthreads();
    #pragma unroll
    for (int off = 32; off > 0; off >>= 1) {
        if (threadIdx.x < off) sred[threadIdx.x] += sred[threadIdx.x + off];
        __syncthreads();
    }
    if (threadIdx.x == 0) atomicAdd(&g_sum, sred[0]);
}

// ---------------------------------------------------------------------------
// Kernel 3: reduce fy with 256 threads (taps split in half per iy), scale
// inline (g_sum final at launch). No grid re-zero here (k_zero owns it).
#define SPAD(i) ((i) + ((i) >> 2))
__global__ __launch_bounds__(256)
void k_pass2(float* __restrict__ out,
             const float* __restrict__ ex,
             const float* __restrict__ ey)
{
    __shared__ float sW[NTAP], sWp[NTAP];
    __shared__ float sBa[NF + NF / 4], sBb[NF + NF / 4];
    __shared__ float sPart[256];
    __shared__ float s_scale;

    const int tid = threadIdx.x;
    const int ix  = blockIdx.x;
    const int iy  = tid & 127;
    const int hf  = tid >> 7;

    if (tid < NTAP) { sW[tid] = g_W[TAP0 + tid]; sWp[tid] = g_Wp[TAP0 + tid]; }
    if (tid == 255) {
        float dxw = ex[1] - ex[0];
        float dyw = ey[1] - ey[0];
        s_scale = 1.0f / (g_sum * dxw * dyw);
    }
    const float2* brow = g_Bt2 + (size_t)ix * NF;
    #pragma unroll
    for (int i = tid; i < NF; i += 256) {
        float2 v = brow[i];
        sBa[SPAD(i)] = v.x;
        sBb[SPAD(i)] = v.y;
    }
    __syncthreads();

    const int t0   = hf * (NTAP / 2);
    const int base = Q * iy + TAP0;                 // max fy index 563 < NF
    float a0 = 0.f, a1 = 0.f;
    #pragma unroll
    for (int t = t0; t < t0 + NTAP / 2; t += 2) {
        a0 = fmaf(sW[t+0], sBa[SPAD(base+t+0)], fmaf(sWp[t+0], sBb[SPAD(base+t+0)], a0));
        a1 = fmaf(sW[t+1], sBa[SPAD(base+t+1)], fmaf(sWp[t+1], sBb[SPAD(base+t+1)], a1));
    }
    sPart[tid] = a0 + a1;
    __syncthreads();
    if (tid < 128)
        out[(size_t)ix * NB + tid] = (sPart[tid] + sPart[tid + 128]) * s_scale;
}

// ---------------------------------------------------------------------------
extern "C" void kernel_launch(void* const* d_in, const int* in_sizes, int n_in,
                              void* d_out, int out_size)
{
    const float* x  = (const float*)d_in[0];
    const float* ex = (const float*)d_in[1];
    const float* ey = (const float*)d_in[2];
    float* out = (float*)d_out;

    int n = in_sizes[0] / 6;

    k_zero<<<512, 256>>>();
    k_deposit<<<(n + 511) / 512, 256>>>(x, ex, ey, n);
    k_pass1<<<dim3(NB / ISEG, NF / 64), 64>>>();
    k_pass2<<<NB, 256>>>(out, ex, ey);
}

// round 14
// speedup vs baseline: 1.1223x; 1.0571x over previous
#include <cuda_runtime.h>
#include <cuda_fp16.h>
#include <cstdint>
#include <math.h>

// Histogram2D via first-moment particle deposit + exact separable erf-CDF
// convolution with derivative correction, q=4 fine cells per bin.
// Four kernels:
//   0) k_zero: zero fine grid, build W/W'/Cw/Cwp tables, reset g_sum.
//   1) k_deposit: ONE red.global.add.noftz.v2.f16x2 per point into an 8-byte
//      fine cell (count/dy/dx in f16; count exact), 1 pt/thread, full grid.
//   2) k_pass1: reduce fx -> (Ba,Bb)[ix][fy] (ISEG=8, 144 CTAs); each CTA adds
//      its exact share of the normalization sum to g_sum.
//   3) k_pass2: reduce fy; grid (128 ix, 2 iy-halves) = 256 CTAs, each stages
//      only its 296-cell fy window; 128 thr = 64 iy x 2 tap-halves; scale inline.
// Error model (validated R7-R13): ~1.46e-4 at q=4 with f16 moments.

#define NB    128
#define Q     4
#define PADB  8                     // padding in bins
#define PAD   (PADB*Q)              // 32 fine cells
#define NF    (NB*Q + 2*PAD)        // 576 fine cells per axis
#define TAP0  12                    // first tap (zc = -4.875 bins)
#define NTAP  44                    // support ~ +/-5 bins (tail < 3e-7)
#define ISEG  8                     // ix outputs per pass1 CTA
#define ERANGE (Q*ISEG + NTAP - Q)  // 72 fine rows read per pass1 CTA
#define NSTG  (Q*63 + NTAP)         // 296 staged cells per pass2 CTA

__device__ float4 g_fg4[(NF * NF) / 2]; // fine grid, 2 cells per float4, 2.65 MB
__device__ float2 g_Bt2[NB * NF];       // pass1 output (Ba,Bb)[ix][fy], 590 KB
__device__ float  g_W[64];              // kernel tap table (bin units)
__device__ float  g_Wp[64];             // d/dz of tap table
__device__ float  g_Cw[NF];             // Cw[fy]  = sum_iy W (fy - Q*iy - TAP0)
__device__ float  g_Cwp[NF];            // Cwp[fy] = sum_iy W'(fy - Q*iy - TAP0)
__device__ float  g_sum;

// ---------------------------------------------------------------------------
// Kernel 0: zero the fine grid; block 0 also builds tables and resets g_sum.
__global__ __launch_bounds__(256)
void k_zero()
{
    const float4 z = make_float4(0.f, 0.f, 0.f, 0.f);
    const int total = (NF * NF) / 2;
    for (int i = blockIdx.x * 256 + threadIdx.x; i < total; i += gridDim.x * 256)
        g_fg4[i] = z;

    if (blockIdx.x == 0) {
        const int tid = threadIdx.x;
        if (tid < 64) {
            float zc = ((float)tid + 0.5f) * (1.0f / (float)Q) - (float)PADB;
            const float is2 = 0.70710678118654752f;     // 1/sqrt(2), sigma=1 bin
            g_W[tid] = 0.5f * (erff((1.0f - zc) * is2) - erff((-zc) * is2));
            const float inv_s2pi = 0.3989422804014327f; // 1/sqrt(2*pi)
            g_Wp[tid] = inv_s2pi * (expf(-0.5f * zc * zc)
                                  - expf(-0.5f * (1.0f - zc) * (1.0f - zc)));
        }
        if (tid == 64) g_sum = 0.0f;
        __syncthreads();
        for (int fy = tid; fy < NF; fy += 256) {
            float cw = 0.f, cwp = 0.f;
            #pragma unroll 4
            for (int iy = 0; iy < NB; iy++) {
                int t = fy - Q * iy - TAP0;
                if (t >= 0 && t < NTAP) {
                    cw  += g_W[TAP0 + t];
                    cwp += g_Wp[TAP0 + t];
                }
            }
            g_Cw[fy]  = cw;
            g_Cwp[fy] = cwp;
        }
    }
}

// ---------------------------------------------------------------------------
// Kernel 1: deposit, 1 point per thread (max occupancy), one vector RED.
__global__ __launch_bounds__(256)
void k_deposit(const float* __restrict__ x,
               const float* __restrict__ ex,
               const float* __restrict__ ey,
               int n)
{
    const float lox = ex[0], dx = ex[1] - ex[0];
    const float loy = ey[0], dy = ey[1] - ey[0];
    const float sx = (float)Q / dx;
    const float sy = (float)Q / dy;

    int p = blockIdx.x * 256 + threadIdx.x;
    if (p >= n) return;

    float2 u = *reinterpret_cast<const float2*>(x + (size_t)p * 6);

    float pfx = (u.x - lox) * sx + (float)PAD;
    float pfy = (u.y - loy) * sy + (float)PAD;
    float cfx = floorf(pfx), cfy = floorf(pfy);
    int cx = (int)cfx, cy = (int)cfy;
    if ((unsigned)cx >= NF || (unsigned)cy >= NF) return;  // mass < 1e-8

    float dxb = (pfx - cfx - 0.5f) * (1.0f / (float)Q);    // bin units
    float dyb = (pfy - cfy - 0.5f) * (1.0f / (float)Q);

    // cell = [count | dyb | dxb | pad] as 2 x f16x2, ONE vector RED.
    __half2 h0 = __floats2half2_rn(1.0f, dyb);   // low = count, high = M01
    __half2 h1 = __floats2half2_rn(dxb, 0.0f);   // low = M10
    uint32_t r0 = *reinterpret_cast<uint32_t*>(&h0);
    uint32_t r1 = *reinterpret_cast<uint32_t*>(&h1);
    char* cell = reinterpret_cast<char*>(g_fg4) + ((size_t)cx * NF + cy) * 8;
    asm volatile("red.global.add.noftz.v2.f16x2 [%0], {%1, %2};"
                 :: "l"(cell), "r"(r0), "r"(r1) : "memory");
}

// ---------------------------------------------------------------------------
// Kernel 2: reduce fx (R9's loop shape: ISEG=8, unroll 4); halo-redundant
// reads, no atomics on Bt. Each CTA adds its exact share of the sum to g_sum.
__global__ __launch_bounds__(64)
void k_pass1()
{
    __shared__ float sW[NTAP], sWp[NTAP];
    __shared__ float sred[64];
    if (threadIdx.x < NTAP) {
        sW[threadIdx.x]  = g_W[TAP0 + threadIdx.x];
        sWp[threadIdx.x] = g_Wp[TAP0 + threadIdx.x];
    }
    __syncthreads();

    const int fy = blockIdx.y * 64 + threadIdx.x;   // < NF (9*64 = 576)
    const int I0 = blockIdx.x * ISEG;
    const uint2* col = reinterpret_cast<const uint2*>(g_fg4) + fy;

    float2 acc[ISEG];
    #pragma unroll
    for (int s = 0; s < ISEG; s++) acc[s] = make_float2(0.f, 0.f);

    #pragma unroll 4
    for (int e = 0; e < ERANGE; e++) {
        const int fx = I0 * Q + TAP0 + e;           // max 563 < NF
        uint2 c = col[(size_t)fx * NF];
        __half2 h0 = *reinterpret_cast<__half2*>(&c.x);
        __half2 h1 = *reinterpret_cast<__half2*>(&c.y);
        float2 f0 = __half22float2(h0);             // (M00, M01)
        float2 f1 = __half22float2(h1);             // (M10, -)
        #pragma unroll
        for (int s = 0; s < ISEG; s++) {
            int t = e - Q * s;                      // tap offset from TAP0
            if (t >= 0 && t < NTAP) {
                acc[s].x = fmaf(sW[t], f0.x, fmaf(sWp[t], f1.x, acc[s].x));
                acc[s].y = fmaf(sW[t], f0.y, acc[s].y);
            }
        }
    }

    float pa = 0.f, pb = 0.f;
    #pragma unroll
    for (int s = 0; s < ISEG; s++) {
        g_Bt2[(size_t)(I0 + s) * NF + fy] = acc[s];
        pa += acc[s].x;
        pb += acc[s].y;
    }

    sred[threadIdx.x] = g_Cw[fy] * pa + g_Cwp[fy] * pb;
    __syncthreads();
    #pragma unroll
    for (int off = 32; off > 0; off >>= 1) {
        if (threadIdx.x < off) sred[threadIdx.x] += sred[threadIdx.x + off];
        __syncthreads();
    }
    if (threadIdx.x == 0) atomicAdd(&g_sum, sred[0]);
}

// ---------------------------------------------------------------------------
// Kernel 3: reduce fy.  Grid (NB, 2): blockIdx.y = iy-half. Each CTA stages
// only the NSTG-cell window its 64 iy outputs touch; 128 threads = 64 iy x
// 2 tap-halves; inline scale by 1/(g_sum*dx*dy) (g_sum final at launch).
#define SPAD(i) ((i) + ((i) >> 2))
__global__ __launch_bounds__(128)
void k_pass2(float* __restrict__ out,
             const float* __restrict__ ex,
             const float* __restrict__ ey)
{
    __shared__ float sW[NTAP], sWp[NTAP];
    __shared__ float sBa[SPAD(NSTG) + 1], sBb[SPAD(NSTG) + 1];
    __shared__ float sPart[128];
    __shared__ float s_scale;

    const int tid = threadIdx.x;
    const int ix  = blockIdx.x;
    const int h   = blockIdx.y;          // iy half: iy = h*64 + iyl
    const int iyl = tid & 63;
    const int hf  = tid >> 6;            // tap half

    if (tid < NTAP) { sW[tid] = g_W[TAP0 + tid]; sWp[tid] = g_Wp[TAP0 + tid]; }
    if (tid == 127) {
        float dxw = ex[1] - ex[0];
        float dyw = ey[1] - ey[0];
        s_scale = 1.0f / (g_sum * dxw * dyw);
    }

    // Stage window: fy in [fy0, fy0 + NSTG), fy0 = Q*(h*64) + TAP0.
    const int fy0 = h * 256 + TAP0;
    const float2* brow = g_Bt2 + (size_t)ix * NF + fy0;
    #pragma unroll
    for (int i = tid; i < NSTG; i += 128) {
        float2 v = brow[i];
        sBa[SPAD(i)] = v.x;
        sBb[SPAD(i)] = v.y;
    }
    __syncthreads();

    const int base = Q * iyl;            // window-local; max 252+43 = 295 < NSTG
    const int t0   = hf * (NTAP / 2);
    float a0 = 0.f, a1 = 0.f;
    #pragma unroll
    for (int t = t0; t < t0 + NTAP / 2; t += 2) {
        a0 = fmaf(sW[t+0], sBa[SPAD(base+t+0)], fmaf(sWp[t+0], sBb[SPAD(base+t+0)], a0));
        a1 = fmaf(sW[t+1], sBa[SPAD(base+t+1)], fmaf(sWp[t+1], sBb[SPAD(base+t+1)], a1));
    }
    sPart[tid] = a0 + a1;
    __syncthreads();
    if (tid < 64)
        out[(size_t)ix * NB + h * 64 + tid] = (sPart[tid] + sPart[tid + 64]) * s_scale;
}

// ---------------------------------------------------------------------------
extern "C" void kernel_launch(void* const* d_in, const int* in_sizes, int n_in,
                              void* d_out, int out_size)
{
    const float* x  = (const float*)d_in[0];
    const float* ex = (const float*)d_in[1];
    const float* ey = (const float*)d_in[2];
    float* out = (float*)d_out;

    int n = in_sizes[0] / 6;

    k_zero<<<512, 256>>>();
    k_deposit<<<(n + 255) / 256, 256>>>(x, ex, ey, n);
    k_pass1<<<dim3(NB / ISEG, NF / 64), 64>>>();
    k_pass2<<<dim3(NB, 2), 128>>>(out, ex, ey);
}

// round 15
// speedup vs baseline: 1.3482x; 1.2013x over previous
#include <cuda_runtime.h>
#include <cuda_fp16.h>
#include <cstdint>
#include <math.h>

// Histogram2D via first-moment particle deposit + exact separable erf-CDF
// convolution with derivative correction, q=4 fine cells per bin.
// Four kernels:
//   0) k_zero: zero fine grid, build W/W'/Cw/Cwp tables, reset g_sum.
//   1) k_deposit: x staged through smem via coalesced float4 loads (12KB/CTA),
//      then ONE red.global.add.noftz.v2.f16x2 per point into an 8-byte fine
//      cell (count/dy/dx in f16; count exact).
//   2) k_pass1: reduce fx -> (Ba,Bb)[ix][fy], ISEG=2 (576 CTAs, ~8 warps/SM);
//      each CTA adds its exact share of the normalization sum to g_sum.
//   3) k_pass2: reduce fy; grid (128 ix, 2 iy-halves), 296-cell smem window,
//      128 thr = 64 iy x 2 tap-halves; inline scale by 1/(g_sum*dx*dy).
// Error model (validated R7-R14): ~1.46e-4 at q=4 with f16 moments.

#define NB    128
#define Q     4
#define PADB  8                     // padding in bins
#define PAD   (PADB*Q)              // 32 fine cells
#define NF    (NB*Q + 2*PAD)        // 576 fine cells per axis
#define TAP0  12                    // first tap (zc = -4.875 bins)
#define NTAP  44                    // support ~ +/-5 bins (tail < 3e-7)
#define ISEG  2                     // ix outputs per pass1 CTA
#define ERANGE (Q*ISEG + NTAP - Q)  // 48 fine rows read per pass1 CTA
#define NSTG  (Q*63 + NTAP)         // 296 staged cells per pass2 CTA
#define PPC   512                   // points per deposit CTA

__device__ float4 g_fg4[(NF * NF) / 2]; // fine grid, 2 cells per float4, 2.65 MB
__device__ float2 g_Bt2[NB * NF];       // pass1 output (Ba,Bb)[ix][fy], 590 KB
__device__ float  g_W[64];              // kernel tap table (bin units)
__device__ float  g_Wp[64];             // d/dz of tap table
__device__ float  g_Cw[NF];             // Cw[fy]  = sum_iy W (fy - Q*iy - TAP0)
__device__ float  g_Cwp[NF];            // Cwp[fy] = sum_iy W'(fy - Q*iy - TAP0)
__device__ float  g_sum;

// ---------------------------------------------------------------------------
// Kernel 0: zero the fine grid; block 0 also builds tables and resets g_sum.
__global__ __launch_bounds__(256)
void k_zero()
{
    const float4 z = make_float4(0.f, 0.f, 0.f, 0.f);
    const int total = (NF * NF) / 2;
    for (int i = blockIdx.x * 256 + threadIdx.x; i < total; i += gridDim.x * 256)
        g_fg4[i] = z;

    if (blockIdx.x == 0) {
        const int tid = threadIdx.x;
        if (tid < 64) {
            float zc = ((float)tid + 0.5f) * (1.0f / (float)Q) - (float)PADB;
            const float is2 = 0.70710678118654752f;     // 1/sqrt(2), sigma=1 bin
            g_W[tid] = 0.5f * (erff((1.0f - zc) * is2) - erff((-zc) * is2));
            const float inv_s2pi = 0.3989422804014327f; // 1/sqrt(2*pi)
            g_Wp[tid] = inv_s2pi * (expf(-0.5f * zc * zc)
                                  - expf(-0.5f * (1.0f - zc) * (1.0f - zc)));
        }
        if (tid == 64) g_sum = 0.0f;
        __syncthreads();
        for (int fy = tid; fy < NF; fy += 256) {
            float cw = 0.f, cwp = 0.f;
            #pragma unroll 4
            for (int iy = 0; iy < NB; iy++) {
                int t = fy - Q * iy - TAP0;
                if (t >= 0 && t < NTAP) {
                    cw  += g_W[TAP0 + t];
                    cwp += g_Wp[TAP0 + t];
                }
            }
            g_Cw[fy]  = cw;
            g_Cwp[fy] = cwp;
        }
    }
}

// ---------------------------------------------------------------------------
// Kernel 1: deposit. Coalesced float4 staging of x into smem, then one
// vector RED per point.
__global__ __launch_bounds__(256)
void k_deposit(const float* __restrict__ x,
               const float* __restrict__ ex,
               const float* __restrict__ ey,
               int n)
{
    __shared__ float sx_[PPC * 6];          // 12 KB chunk of x

    const int tid = threadIdx.x;
    const int nfl = n * 6;                  // total floats in x
    const size_t base_f = (size_t)blockIdx.x * (PPC * 6);

    // Stage: 768 float4 per CTA, perfectly coalesced (x is 16B-aligned and
    // n*24 is a multiple of 16).
    const float4* src = reinterpret_cast<const float4*>(x + base_f);
    #pragma unroll
    for (int k = 0; k < 3; k++) {
        int fi = (k * 256 + tid) * 4;       // float offset within chunk
        float4 v = make_float4(1e30f, 1e30f, 1e30f, 1e30f);
        if (base_f + fi + 4 <= (size_t)nfl) v = src[k * 256 + tid];
        reinterpret_cast<float4*>(sx_)[k * 256 + tid] = v;
    }
    __syncthreads();

    const float lox = ex[0], dx = ex[1] - ex[0];
    const float loy = ey[0], dy = ey[1] - ey[0];
    const float sxc = (float)Q / dx;
    const float syc = (float)Q / dy;

    #pragma unroll
    for (int k = 0; k < 2; k++) {
        const int l = k * 256 + tid;        // local point index
        float ux = sx_[l * 6 + 0];
        float uy = sx_[l * 6 + 1];

        float pfx = (ux - lox) * sxc + (float)PAD;
        float pfy = (uy - loy) * syc + (float)PAD;
        float cfx = floorf(pfx), cfy = floorf(pfy);
        int cx = (int)cfx, cy = (int)cfy;
        if ((unsigned)cx >= NF || (unsigned)cy >= NF) continue; // also OOB pads

        float dxb = (pfx - cfx - 0.5f) * (1.0f / (float)Q);     // bin units
        float dyb = (pfy - cfy - 0.5f) * (1.0f / (float)Q);

        // cell = [count | dyb | dxb | pad] as 2 x f16x2, ONE vector RED.
        __half2 h0 = __floats2half2_rn(1.0f, dyb);  // low = count, high = M01
        __half2 h1 = __floats2half2_rn(dxb, 0.0f);  // low = M10
        uint32_t r0 = *reinterpret_cast<uint32_t*>(&h0);
        uint32_t r1 = *reinterpret_cast<uint32_t*>(&h1);
        char* cell = reinterpret_cast<char*>(g_fg4) + ((size_t)cx * NF + cy) * 8;
        asm volatile("red.global.add.noftz.v2.f16x2 [%0], {%1, %2};"
                     :: "l"(cell), "r"(r0), "r"(r1) : "memory");
    }
}

// ---------------------------------------------------------------------------
// Kernel 2: reduce fx; ISEG=2 -> 64 x-segments x 9 fy-tiles = 576 CTAs of
// 64 threads (~8 warps/SM for latency hiding). Halo-redundant reads, no
// atomics on Bt. Each CTA adds its exact share of the sum to g_sum.
__global__ __launch_bounds__(64)
void k_pass1()
{
    __shared__ float sW[NTAP], sWp[NTAP];
    __shared__ float sred[64];
    if (threadIdx.x < NTAP) {
        sW[threadIdx.x]  = g_W[TAP0 + threadIdx.x];
        sWp[threadIdx.x] = g_Wp[TAP0 + threadIdx.x];
    }
    __syncthreads();

    const int fy = blockIdx.y * 64 + threadIdx.x;   // < NF (9*64 = 576)
    const int I0 = blockIdx.x * ISEG;
    const uint2* col = reinterpret_cast<const uint2*>(g_fg4) + fy;

    float2 acc[ISEG];
    #pragma unroll
    for (int s = 0; s < ISEG; s++) acc[s] = make_float2(0.f, 0.f);

    #pragma unroll 4
    for (int e = 0; e < ERANGE; e++) {
        const int fx = I0 * Q + TAP0 + e;           // max 504+12+47 = 563 < NF
        uint2 c = col[(size_t)fx * NF];
        __half2 h0 = *reinterpret_cast<__half2*>(&c.x);
        __half2 h1 = *reinterpret_cast<__half2*>(&c.y);
        float2 f0 = __half22float2(h0);             // (M00, M01)
        float2 f1 = __half22float2(h1);             // (M10, -)
        #pragma unroll
        for (int s = 0; s < ISEG; s++) {
            int t = e - Q * s;                      // tap offset from TAP0
            if (t >= 0 && t < NTAP) {
                acc[s].x = fmaf(sW[t], f0.x, fmaf(sWp[t], f1.x, acc[s].x));
                acc[s].y = fmaf(sW[t], f0.y, acc[s].y);
            }
        }
    }

    float pa = 0.f, pb = 0.f;
    #pragma unroll
    for (int s = 0; s < ISEG; s++) {
        g_Bt2[(size_t)(I0 + s) * NF + fy] = acc[s];
        pa += acc[s].x;
        pb += acc[s].y;
    }

    sred[threadIdx.x] = g_Cw[fy] * pa + g_Cwp[fy] * pb;
    __syncthreads();
    #pragma unroll
    for (int off = 32; off > 0; off >>= 1) {
        if (threadIdx.x < off) sred[threadIdx.x] += sred[threadIdx.x + off];
        __syncthreads();
    }
    if (threadIdx.x == 0) atomicAdd(&g_sum, sred[0]);
}

// ---------------------------------------------------------------------------
// Kernel 3: reduce fy.  Grid (NB, 2): blockIdx.y = iy-half. Each CTA stages
// only the NSTG-cell window its 64 iy outputs touch; 128 threads = 64 iy x
// 2 tap-halves; inline scale by 1/(g_sum*dx*dy) (g_sum final at launch).
#define SPAD(i) ((i) + ((i) >> 2))
__global__ __launch_bounds__(128)
void k_pass2(float* __restrict__ out,
             const float* __restrict__ ex,
             const float* __restrict__ ey)
{
    __shared__ float sW[NTAP], sWp[NTAP];
    __shared__ float sBa[SPAD(NSTG) + 1], sBb[SPAD(NSTG) + 1];
    __shared__ float sPart[128];
    __shared__ float s_scale;

    const int tid = threadIdx.x;
    const int ix  = blockIdx.x;
    const int h   = blockIdx.y;          // iy half: iy = h*64 + iyl
    const int iyl = tid & 63;
    const int hf  = tid >> 6;            // tap half

    if (tid < NTAP) { sW[tid] = g_W[TAP0 + tid]; sWp[tid] = g_Wp[TAP0 + tid]; }
    if (tid == 127) {
        float dxw = ex[1] - ex[0];
        float dyw = ey[1] - ey[0];
        s_scale = 1.0f / (g_sum * dxw * dyw);
    }

    // Stage window: fy in [fy0, fy0 + NSTG), fy0 = Q*(h*64) + TAP0.
    const int fy0 = h * 256 + TAP0;
    const float2* brow = g_Bt2 + (size_t)ix * NF + fy0;
    #pragma unroll
    for (int i = tid; i < NSTG; i += 128) {
        float2 v = brow[i];
        sBa[SPAD(i)] = v.x;
        sBb[SPAD(i)] = v.y;
    }
    __syncthreads();

    const int base = Q * iyl;            // window-local; max 252+43 = 295 < NSTG
    const int t0   = hf * (NTAP / 2);
    float a0 = 0.f, a1 = 0.f;
    #pragma unroll
    for (int t = t0; t < t0 + NTAP / 2; t += 2) {
        a0 = fmaf(sW[t+0], sBa[SPAD(base+t+0)], fmaf(sWp[t+0], sBb[SPAD(base+t+0)], a0));
        a1 = fmaf(sW[t+1], sBa[SPAD(base+t+1)], fmaf(sWp[t+1], sBb[SPAD(base+t+1)], a1));
    }
    sPart[tid] = a0 + a1;
    __syncthreads();
    if (tid < 64)
        out[(size_t)ix * NB + h * 64 + tid] = (sPart[tid] + sPart[tid + 64]) * s_scale;
}

// ---------------------------------------------------------------------------
extern "C" void kernel_launch(void* const* d_in, const int* in_sizes, int n_in,
                              void* d_out, int out_size)
{
    const float* x  = (const float*)d_in[0];
    const float* ex = (const float*)d_in[1];
    const float* ey = (const float*)d_in[2];
    float* out = (float*)d_out;

    int n = in_sizes[0] / 6;

    k_zero<<<512, 256>>>();
    k_deposit<<<(n + PPC - 1) / PPC, 256>>>(x, ex, ey, n);
    k_pass1<<<dim3(NB / ISEG, NF / 64), 64>>>();
    k_pass2<<<dim3(NB, 2), 128>>>(out, ex, ey);
}

// round 16
// speedup vs baseline: 1.5783x; 1.1707x over previous
#include <cuda_runtime.h>
#include <cuda_fp16.h>
#include <cstdint>
#include <math.h>

// Histogram2D via first-moment particle deposit + exact separable erf-CDF
// convolution with derivative correction, q=4 fine cells per bin.
// THREE kernels (small-kernel launch floor ~3-5us dominates at this scale):
//   1) k_deposit: x staged through smem via coalesced float4 loads (12KB/CTA),
//      ONE red.global.add.noftz.v2.f16x2 per point into an 8-byte fine cell
//      (count/dy/dx in f16; count exact). Last block builds W/W'/Cw/Cwp and
//      resets g_sum (consumed only by later kernels).
//   2) k_pass1: reduce fx -> (Ba,Bb)[ix][fy], ISEG=2 (576 CTAs, ~8 warps/SM);
//      each CTA adds its exact share of the normalization sum to g_sum.
//   3) k_pass2: reduce fy; grid (128 ix, 2 iy-halves), 296-cell smem window,
//      128 thr = 64 iy x 2 tap-halves; inline scale by 1/(g_sum*dx*dy);
//      re-zeroes the fine grid for the next replay at the end (first call is
//      covered by static zero-init of device globals).
// Error model (validated R7-R15): ~1.457e-4 at q=4 with f16 moments.

#define NB    128
#define Q     4
#define PADB  8                     // padding in bins
#define PAD   (PADB*Q)              // 32 fine cells
#define NF    (NB*Q + 2*PAD)        // 576 fine cells per axis
#define TAP0  12                    // first tap (zc = -4.875 bins)
#define NTAP  44                    // support ~ +/-5 bins (tail < 3e-7)
#define ISEG  2                     // ix outputs per pass1 CTA
#define ERANGE (Q*ISEG + NTAP - Q)  // 48 fine rows read per pass1 CTA
#define NSTG  (Q*63 + NTAP)         // 296 staged cells per pass2 CTA
#define PPC   512                   // points per deposit CTA

__device__ float4 g_fg4[(NF * NF) / 2]; // fine grid, 2 cells per float4, 2.65 MB
__device__ float2 g_Bt2[NB * NF];       // pass1 output (Ba,Bb)[ix][fy], 590 KB
__device__ float  g_W[64];              // kernel tap table (bin units)
__device__ float  g_Wp[64];             // d/dz of tap table
__device__ float  g_Cw[NF];             // Cw[fy]  = sum_iy W (fy - Q*iy - TAP0)
__device__ float  g_Cwp[NF];            // Cwp[fy] = sum_iy W'(fy - Q*iy - TAP0)
__device__ float  g_sum;

// ---------------------------------------------------------------------------
// Kernel 1: deposit (blocks [0, G-1)) + table block (last block).
__global__ __launch_bounds__(256)
void k_deposit(const float* __restrict__ x,
               const float* __restrict__ ex,
               const float* __restrict__ ey,
               int n)
{
    if (blockIdx.x == gridDim.x - 1) {
        // ---- table block: W/W', Cw/Cwp, reset g_sum (used by pass1/pass2) ----
        const int tid = threadIdx.x;
        if (tid < 64) {
            float zc = ((float)tid + 0.5f) * (1.0f / (float)Q) - (float)PADB;
            const float is2 = 0.70710678118654752f;     // 1/sqrt(2), sigma=1 bin
            g_W[tid] = 0.5f * (erff((1.0f - zc) * is2) - erff((-zc) * is2));
            const float inv_s2pi = 0.3989422804014327f; // 1/sqrt(2*pi)
            g_Wp[tid] = inv_s2pi * (expf(-0.5f * zc * zc)
                                  - expf(-0.5f * (1.0f - zc) * (1.0f - zc)));
        }
        if (tid == 64) g_sum = 0.0f;
        __syncthreads();
        for (int fy = tid; fy < NF; fy += 256) {
            float cw = 0.f, cwp = 0.f;
            #pragma unroll 4
            for (int iy = 0; iy < NB; iy++) {
                int t = fy - Q * iy - TAP0;
                if (t >= 0 && t < NTAP) {
                    cw  += g_W[TAP0 + t];
                    cwp += g_Wp[TAP0 + t];
                }
            }
            g_Cw[fy]  = cw;
            g_Cwp[fy] = cwp;
        }
        return;
    }

    __shared__ float sx_[PPC * 6];          // 12 KB chunk of x

    const int tid = threadIdx.x;
    const int nfl = n * 6;                  // total floats in x
    const size_t base_f = (size_t)blockIdx.x * (PPC * 6);

    // Stage: 768 float4 per CTA, perfectly coalesced.
    const float4* src = reinterpret_cast<const float4*>(x + base_f);
    #pragma unroll
    for (int k = 0; k < 3; k++) {
        int fi = (k * 256 + tid) * 4;       // float offset within chunk
        float4 v = make_float4(1e30f, 1e30f, 1e30f, 1e30f);
        if (base_f + fi + 4 <= (size_t)nfl) v = src[k * 256 + tid];
        reinterpret_cast<float4*>(sx_)[k * 256 + tid] = v;
    }
    __syncthreads();

    const float lox = ex[0], dx = ex[1] - ex[0];
    const float loy = ey[0], dy = ey[1] - ey[0];
    const float sxc = (float)Q / dx;
    const float syc = (float)Q / dy;

    #pragma unroll
    for (int k = 0; k < 2; k++) {
        const int l = k * 256 + tid;        // local point index
        float ux = sx_[l * 6 + 0];
        float uy = sx_[l * 6 + 1];

        float pfx = (ux - lox) * sxc + (float)PAD;
        float pfy = (uy - loy) * syc + (float)PAD;
        float cfx = floorf(pfx), cfy = floorf(pfy);
        int cx = (int)cfx, cy = (int)cfy;
        if ((unsigned)cx >= NF || (unsigned)cy >= NF) continue; // also OOB pads

        float dxb = (pfx - cfx - 0.5f) * (1.0f / (float)Q);     // bin units
        float dyb = (pfy - cfy - 0.5f) * (1.0f / (float)Q);

        // cell = [count | dyb | dxb | pad] as 2 x f16x2, ONE vector RED.
        __half2 h0 = __floats2half2_rn(1.0f, dyb);  // low = count, high = M01
        __half2 h1 = __floats2half2_rn(dxb, 0.0f);  // low = M10
        uint32_t r0 = *reinterpret_cast<uint32_t*>(&h0);
        uint32_t r1 = *reinterpret_cast<uint32_t*>(&h1);
        char* cell = reinterpret_cast<char*>(g_fg4) + ((size_t)cx * NF + cy) * 8;
        asm volatile("red.global.add.noftz.v2.f16x2 [%0], {%1, %2};"
                     :: "l"(cell), "r"(r0), "r"(r1) : "memory");
    }
}

// ---------------------------------------------------------------------------
// Kernel 2: reduce fx; ISEG=2 -> 64 x-segments x 9 fy-tiles = 576 CTAs of
// 64 threads. Halo-redundant reads, no atomics on Bt. Each CTA adds its
// exact share of the normalization sum to g_sum.
__global__ __launch_bounds__(64)
void k_pass1()
{
    __shared__ float sW[NTAP], sWp[NTAP];
    __shared__ float sred[64];
    if (threadIdx.x < NTAP) {
        sW[threadIdx.x]  = g_W[TAP0 + threadIdx.x];
        sWp[threadIdx.x] = g_Wp[TAP0 + threadIdx.x];
    }
    __syncthreads();

    const int fy = blockIdx.y * 64 + threadIdx.x;   // < NF (9*64 = 576)
    const int I0 = blockIdx.x * ISEG;
    const uint2* col = reinterpret_cast<const uint2*>(g_fg4) + fy;

    float2 acc[ISEG];
    #pragma unroll
    for (int s = 0; s < ISEG; s++) acc[s] = make_float2(0.f, 0.f);

    #pragma unroll 4
    for (int e = 0; e < ERANGE; e++) {
        const int fx = I0 * Q + TAP0 + e;           // max 504+12+47 = 563 < NF
        uint2 c = col[(size_t)fx * NF];
        __half2 h0 = *reinterpret_cast<__half2*>(&c.x);
        __half2 h1 = *reinterpret_cast<__half2*>(&c.y);
        float2 f0 = __half22float2(h0);             // (M00, M01)
        float2 f1 = __half22float2(h1);             // (M10, -)
        #pragma unroll
        for (int s = 0; s < ISEG; s++) {
            int t = e - Q * s;                      // tap offset from TAP0
            if (t >= 0 && t < NTAP) {
                acc[s].x = fmaf(sW[t], f0.x, fmaf(sWp[t], f1.x, acc[s].x));
                acc[s].y = fmaf(sW[t], f0.y, acc[s].y);
            }
        }
    }

    float pa = 0.f, pb = 0.f;
    #pragma unroll
    for (int s = 0; s < ISEG; s++) {
        g_Bt2[(size_t)(I0 + s) * NF + fy] = acc[s];
        pa += acc[s].x;
        pb += acc[s].y;
    }

    sred[threadIdx.x] = g_Cw[fy] * pa + g_Cwp[fy] * pb;
    __syncthreads();
    #pragma unroll
    for (int off = 32; off > 0; off >>= 1) {
        if (threadIdx.x < off) sred[threadIdx.x] += sred[threadIdx.x + off];
        __syncthreads();
    }
    if (threadIdx.x == 0) atomicAdd(&g_sum, sred[0]);
}

// ---------------------------------------------------------------------------
// Kernel 3: reduce fy.  Grid (NB, 2): blockIdx.y = iy-half. Each CTA stages
// only the NSTG-cell window its 64 iy outputs touch; 128 threads = 64 iy x
// 2 tap-halves; inline scale by 1/(g_sum*dx*dy). After the output store,
// the 256 CTAs cooperatively re-zero the fine grid for the next replay.
#define SPAD(i) ((i) + ((i) >> 2))
__global__ __launch_bounds__(128)
void k_pass2(float* __restrict__ out,
             const float* __restrict__ ex,
             const float* __restrict__ ey)
{
    __shared__ float sW[NTAP], sWp[NTAP];
    __shared__ float sBa[SPAD(NSTG) + 1], sBb[SPAD(NSTG) + 1];
    __shared__ float sPart[128];
    __shared__ float s_scale;

    const int tid = threadIdx.x;
    const int ix  = blockIdx.x;
    const int h   = blockIdx.y;          // iy half: iy = h*64 + iyl
    const int iyl = tid & 63;
    const int hf  = tid >> 6;            // tap half

    if (tid < NTAP) { sW[tid] = g_W[TAP0 + tid]; sWp[tid] = g_Wp[TAP0 + tid]; }
    if (tid == 127) {
        float dxw = ex[1] - ex[0];
        float dyw = ey[1] - ey[0];
        s_scale = 1.0f / (g_sum * dxw * dyw);
    }

    // Stage window: fy in [fy0, fy0 + NSTG), fy0 = Q*(h*64) + TAP0.
    const int fy0 = h * 256 + TAP0;
    const float2* brow = g_Bt2 + (size_t)ix * NF + fy0;
    #pragma unroll
    for (int i = tid; i < NSTG; i += 128) {
        float2 v = brow[i];
        sBa[SPAD(i)] = v.x;
        sBb[SPAD(i)] = v.y;
    }
    __syncthreads();

    const int base = Q * iyl;            // window-local; max 252+43 = 295 < NSTG
    const int t0   = hf * (NTAP / 2);
    float a0 = 0.f, a1 = 0.f;
    #pragma unroll
    for (int t = t0; t < t0 + NTAP / 2; t += 2) {
        a0 = fmaf(sW[t+0], sBa[SPAD(base+t+0)], fmaf(sWp[t+0], sBb[SPAD(base+t+0)], a0));
        a1 = fmaf(sW[t+1], sBa[SPAD(base+t+1)], fmaf(sWp[t+1], sBb[SPAD(base+t+1)], a1));
    }
    sPart[tid] = a0 + a1;
    __syncthreads();
    if (tid < 64)
        out[(size_t)ix * NB + h * 64 + tid] = (sPart[tid] + sPart[tid + 64]) * s_scale;

    // Re-zero the fine grid for the next replay (g_fg's last consumer was
    // pass1; ordered by the kernel boundary). ~650 B per thread, coalesced.
    const float4 z = make_float4(0.f, 0.f, 0.f, 0.f);
    const int gcta = h * NB + ix;        // 0..255
    for (int i = gcta * 128 + tid; i < (NF * NF) / 2; i += 256 * 128)
        g_fg4[i] = z;
}

// ---------------------------------------------------------------------------
extern "C" void kernel_launch(void* const* d_in, const int* in_sizes, int n_in,
                              void* d_out, int out_size)
{
    const float* x  = (const float*)d_in[0];
    const float* ex = (const float*)d_in[1];
    const float* ey = (const float*)d_in[2];
    float* out = (float*)d_out;

    int n = in_sizes[0] / 6;

    k_deposit<<<(n + PPC - 1) / PPC + 1, 256>>>(x, ex, ey, n);
    k_pass1<<<dim3(NB / ISEG, NF / 64), 64>>>();
    k_pass2<<<dim3(NB, 2), 128>>>(out, ex, ey);
}